// round 1
// baseline (speedup 1.0000x reference)
#include <cuda_runtime.h>
#include <cstdint>

// GeneralizedInteractionNet: B=2048, F=N=40, D=64, L=3
// out[b,n,D] = sum_d M[n,D,d] * sum_f B0[b,f,D] * sum_i alpha[f,i,n]*Bi[b,i,d]
// with M[n,D,d] = W[n,D,d]*h[n,d]; iterated 3 layers (Bi <- out, B0 = inputs).

#define BB 2048
#define NF 40
#define DD 64
#define NL 3

// Scratch (allocation-free rule: __device__ globals)
__device__ float g_buf0[BB * NF * DD];
__device__ float g_buf1[BB * NF * DD];
__device__ float g_alphaT[NL * NF * NF * NF];   // [l][n][f][i]

// Packed fp32x2 FMA (Blackwell FFMA2) — 2 MACs per FMA-pipe slot.
__device__ __forceinline__ void ffma2(unsigned long long& d,
                                      unsigned long long a,
                                      unsigned long long b) {
    asm("fma.rn.f32x2 %0, %1, %2, %0;" : "+l"(d) : "l"(a), "l"(b));
}
__device__ __forceinline__ float2 u2f(unsigned long long v) {
    return make_float2(__uint_as_float((unsigned)v),
                       __uint_as_float((unsigned)(v >> 32)));
}

// alphaT[l][n][f][i] = alpha[l][f][i][n]  (coalesced per-block loads later)
__global__ void alphaT_kernel(const float* __restrict__ alpha,
                              float* __restrict__ out) {
    int idx = blockIdx.x * blockDim.x + threadIdx.x;
    if (idx >= NL * NF * NF * NF) return;
    int i = idx % NF;
    int f = (idx / NF) % NF;
    int n = (idx / (NF * NF)) % NF;
    int l = idx / (NF * NF * NF);
    out[idx] = alpha[((l * NF + f) * NF + i) * NF + n];
}

// ---- shared memory layout (in floats) ----
#define OFF_BI   0                         // sBi   [40][64]
#define OFF_T    (OFF_BI + NF * DD)        // sT    [40][64]
#define OFF_B0D  (OFF_T + NF * DD)         // sB0d  [40][128]  (each float duplicated)
#define OFF_ALD  (OFF_B0D + NF * 2 * DD)   // sAld  [40][80]   (each float duplicated)
#define OFF_M    (OFF_ALD + NF * 2 * NF)   // sM    [64][68]   (pad 68 vs bank conflicts)
#define MPITCH   68
#define OFF_RED  (OFF_M + DD * MPITCH)     // sRed  [16][64]
#define SMEM_FLOATS (OFF_RED + 16 * DD)
#define SMEM_BYTES  (SMEM_FLOATS * 4)      // 75264 B -> 3 CTAs/SM

__global__ __launch_bounds__(256) void layer_kernel(
    const float* __restrict__ B0g,   // inputs      [B][F][D]
    const float* __restrict__ Big,   // prev output [B][N][D]
    const float* __restrict__ Wg,    // this layer  [N][D][D]
    const float* __restrict__ alTg,  // this layer  [N][F][I]
    const float* __restrict__ hg,    // this layer  [N][D]
    float* __restrict__ outg)        // [B][N][D]
{
    extern __shared__ float sm[];
    float* sBi  = sm + OFF_BI;
    float* sT   = sm + OFF_T;
    float* sB0d = sm + OFF_B0D;
    float* sAld = sm + OFF_ALD;
    float* sM   = sm + OFF_M;
    float* sRed = sm + OFF_RED;

    const int n = blockIdx.x;     // x = n so consecutive blocks share b-slices in L2
    const int b = blockIdx.y;
    const int t  = threadIdx.x;
    const int tx = t & 15;
    const int ty = t >> 4;

    // ---- stage loads ----
    const float* bi = Big + (size_t)b * NF * DD;
    const float* b0 = B0g + (size_t)b * NF * DD;
    for (int v = t; v < NF * DD / 4; v += 256) {
        float4 x = ((const float4*)bi)[v];
        ((float4*)sBi)[v] = x;
        float4 y = ((const float4*)b0)[v];
        ((float4*)sB0d)[2 * v]     = make_float4(y.x, y.x, y.y, y.y);
        ((float4*)sB0d)[2 * v + 1] = make_float4(y.z, y.z, y.w, y.w);
    }
    const float* al = alTg + n * NF * NF;
    for (int v = t; v < NF * NF / 4; v += 256) {
        float4 y = ((const float4*)al)[v];
        ((float4*)sAld)[2 * v]     = make_float4(y.x, y.x, y.y, y.y);
        ((float4*)sAld)[2 * v + 1] = make_float4(y.z, y.z, y.w, y.w);
    }
    const float* wp = Wg + n * DD * DD;
    const float* hp = hg + n * DD;
    for (int v = t; v < DD * DD / 4; v += 256) {
        float4 x = ((const float4*)wp)[v];
        int e = v * 4;
        int Dr = e >> 6;
        int d  = e & 63;
        float4 hv = ((const float4*)hp)[d >> 2];
        x.x *= hv.x; x.y *= hv.y; x.z *= hv.z; x.w *= hv.w;
        *(float4*)&sM[Dr * MPITCH + d] = x;
    }
    __syncthreads();

    // ---- step 2: T[f][d] = sum_i alpha[f][i] * Bi[i][d] ----
    // thread -> d-quad = tx*4 ; f in {ty, ty+16, ty+32(<40)}
    {
        const int dq = tx * 4;
        unsigned long long a00 = 0, a01 = 0, a10 = 0, a11 = 0, a20 = 0, a21 = 0;
        const int f0 = ty, f1 = ty + 16, f2 = ty + 32;
        const bool has2 = (f2 < NF);
        #pragma unroll 4
        for (int i = 0; i < NF; ++i) {
            unsigned long long bA = *(const unsigned long long*)&sBi[i * DD + dq];
            unsigned long long bB = *(const unsigned long long*)&sBi[i * DD + dq + 2];
            unsigned long long al0 = *(const unsigned long long*)&sAld[f0 * 2 * NF + 2 * i];
            ffma2(a00, al0, bA); ffma2(a01, al0, bB);
            unsigned long long al1 = *(const unsigned long long*)&sAld[f1 * 2 * NF + 2 * i];
            ffma2(a10, al1, bA); ffma2(a11, al1, bB);
            if (has2) {
                unsigned long long al2 = *(const unsigned long long*)&sAld[f2 * 2 * NF + 2 * i];
                ffma2(a20, al2, bA); ffma2(a21, al2, bB);
            }
        }
        *(unsigned long long*)&sT[f0 * DD + dq]     = a00;
        *(unsigned long long*)&sT[f0 * DD + dq + 2] = a01;
        *(unsigned long long*)&sT[f1 * DD + dq]     = a10;
        *(unsigned long long*)&sT[f1 * DD + dq + 2] = a11;
        if (has2) {
            *(unsigned long long*)&sT[f2 * DD + dq]     = a20;
            *(unsigned long long*)&sT[f2 * DD + dq + 2] = a21;
        }
    }
    __syncthreads();

    // ---- step 3: G[D][d] = sum_k B0[k][D]*T[k][d]; out[D] = sum_d M[D][d]*G[D][d]
    // thread (ty,tx): D-quad = tx*4, d-quad = ty*4; 4x4 register tile, f32x2-packed over d.
    {
        const int Dq = tx * 4, dq = ty * 4;
        unsigned long long g0A = 0, g0B = 0, g1A = 0, g1B = 0;
        unsigned long long g2A = 0, g2B = 0, g3A = 0, g3B = 0;
        #pragma unroll 2
        for (int k = 0; k < NF; ++k) {
            unsigned long long tA = *(const unsigned long long*)&sT[k * DD + dq];
            unsigned long long tB = *(const unsigned long long*)&sT[k * DD + dq + 2];
            const unsigned long long* bd =
                (const unsigned long long*)&sB0d[k * 2 * DD + 2 * Dq];
            unsigned long long b0d = bd[0], b1d = bd[1], b2d = bd[2], b3d = bd[3];
            ffma2(g0A, b0d, tA); ffma2(g0B, b0d, tB);
            ffma2(g1A, b1d, tA); ffma2(g1B, b1d, tB);
            ffma2(g2A, b2d, tA); ffma2(g2B, b2d, tB);
            ffma2(g3A, b3d, tA); ffma2(g3B, b3d, tB);
        }
        float po[4];
        {
            float2 gA, gB;
            const float* mr;
            gA = u2f(g0A); gB = u2f(g0B); mr = &sM[(Dq + 0) * MPITCH + dq];
            po[0] = gA.x * mr[0] + gA.y * mr[1] + gB.x * mr[2] + gB.y * mr[3];
            gA = u2f(g1A); gB = u2f(g1B); mr = &sM[(Dq + 1) * MPITCH + dq];
            po[1] = gA.x * mr[0] + gA.y * mr[1] + gB.x * mr[2] + gB.y * mr[3];
            gA = u2f(g2A); gB = u2f(g2B); mr = &sM[(Dq + 2) * MPITCH + dq];
            po[2] = gA.x * mr[0] + gA.y * mr[1] + gB.x * mr[2] + gB.y * mr[3];
            gA = u2f(g3A); gB = u2f(g3B); mr = &sM[(Dq + 3) * MPITCH + dq];
            po[3] = gA.x * mr[0] + gA.y * mr[1] + gB.x * mr[2] + gB.y * mr[3];
        }
        *(float4*)&sRed[ty * DD + Dq] = make_float4(po[0], po[1], po[2], po[3]);
    }
    __syncthreads();

    // ---- reduce over the 16 d-groups and store ----
    if (t < DD) {
        float s = 0.f;
        #pragma unroll
        for (int r = 0; r < 16; ++r) s += sRed[r * DD + t];
        outg[((size_t)b * NF + n) * DD + t] = s;
    }
}

extern "C" void kernel_launch(void* const* d_in, const int* in_sizes, int n_in,
                              void* d_out, int out_size) {
    // Identify inputs by element count (robust to ordering)
    const float *inp = nullptr, *Wp = nullptr, *alp = nullptr, *hp = nullptr;
    for (int i = 0; i < n_in; ++i) {
        switch (in_sizes[i]) {
            case BB * NF * DD:      inp = (const float*)d_in[i]; break;  // 5242880
            case NL * NF * DD * DD: Wp  = (const float*)d_in[i]; break;  // 491520
            case NL * NF * NF * NF: alp = (const float*)d_in[i]; break;  // 192000
            case NL * NF * DD:      hp  = (const float*)d_in[i]; break;  // 7680
        }
    }

    float *buf0, *buf1, *alT;
    cudaGetSymbolAddress((void**)&buf0, g_buf0);
    cudaGetSymbolAddress((void**)&buf1, g_buf1);
    cudaGetSymbolAddress((void**)&alT, g_alphaT);

    cudaFuncSetAttribute(layer_kernel,
                         cudaFuncAttributeMaxDynamicSharedMemorySize, SMEM_BYTES);

    alphaT_kernel<<<(NL * NF * NF * NF + 255) / 256, 256>>>(alp, alT);

    dim3 grid(NF, BB);
    layer_kernel<<<grid, 256, SMEM_BYTES>>>(inp, inp,  Wp,
                                            alT,                 hp,              buf0);
    layer_kernel<<<grid, 256, SMEM_BYTES>>>(inp, buf0, Wp + NF * DD * DD,
                                            alT + NF * NF * NF,  hp + NF * DD,    buf1);
    layer_kernel<<<grid, 256, SMEM_BYTES>>>(inp, buf1, Wp + 2 * NF * DD * DD,
                                            alT + 2 * NF * NF * NF, hp + 2 * NF * DD,
                                            (float*)d_out);
}